// round 1
// baseline (speedup 1.0000x reference)
#include <cuda_runtime.h>
#include <math.h>

#define NS_   8192
#define NK_   8192
#define HID_  1024
#define SENT_ 1024
#define TWOH_ 2048
#define RSPLIT 32

__device__ float g_S[(size_t)NS_ * HID_];
__device__ float g_K[(size_t)NK_ * HID_];
__device__ float g_pmax[RSPLIT * NK_];
__device__ float g_psum[RSPLIT * NK_];
__device__ float g_cmax[NK_];
__device__ float g_cinv[NK_];

template <bool TRANS_B>
__global__ __launch_bounds__(256)
void sgemm_kernel(const float* __restrict__ A, const float* __restrict__ B,
                  const float* __restrict__ bias, float* __restrict__ C,
                  int M, int N, int K)
{
    __shared__ float As[16][128];
    __shared__ float Bs[16][128];

    const int t  = threadIdx.x;
    const int bm = blockIdx.y;
    const int bn = blockIdx.x;
    const int tm = t >> 4;
    const int tn = t & 15;
    const int row0 = bm * 128;
    const int col0 = bn * 128;

    float acc[8][8];
#pragma unroll
    for (int r = 0; r < 8; r++)
#pragma unroll
        for (int c = 0; c < 8; c++) acc[r][c] = 0.0f;

    for (int kt = 0; kt < K; kt += 16) {
#pragma unroll
        for (int q = 0; q < 2; q++) {
            int idx = q * 256 + t;
            int r   = idx >> 2;
            int k4  = (idx & 3) * 4;
            float4 v = *(const float4*)&A[(size_t)(row0 + r) * K + kt + k4];
            As[k4 + 0][r] = v.x;
            As[k4 + 1][r] = v.y;
            As[k4 + 2][r] = v.z;
            As[k4 + 3][r] = v.w;
        }
        if (TRANS_B) {
#pragma unroll
            for (int q = 0; q < 2; q++) {
                int idx = q * 256 + t;
                int r   = idx >> 2;
                int k4  = (idx & 3) * 4;
                float4 v = *(const float4*)&B[(size_t)(col0 + r) * K + kt + k4];
                Bs[k4 + 0][r] = v.x;
                Bs[k4 + 1][r] = v.y;
                Bs[k4 + 2][r] = v.z;
                Bs[k4 + 3][r] = v.w;
            }
        } else {
#pragma unroll
            for (int q = 0; q < 2; q++) {
                int idx = q * 256 + t;
                int kr  = idx >> 5;
                int c4  = (idx & 31) * 4;
                float4 v = *(const float4*)&B[(size_t)(kt + kr) * N + col0 + c4];
                *(float4*)&Bs[kr][c4] = v;
            }
        }
        __syncthreads();

#pragma unroll
        for (int kk = 0; kk < 16; kk++) {
            float a[8], b[8];
            *(float4*)&a[0] = *(const float4*)&As[kk][tm * 8];
            *(float4*)&a[4] = *(const float4*)&As[kk][tm * 8 + 4];
            *(float4*)&b[0] = *(const float4*)&Bs[kk][tn * 8];
            *(float4*)&b[4] = *(const float4*)&Bs[kk][tn * 8 + 4];
#pragma unroll
            for (int r = 0; r < 8; r++)
#pragma unroll
                for (int c = 0; c < 8; c++)
                    acc[r][c] = fmaf(a[r], b[c], acc[r][c]);
        }
        __syncthreads();
    }

#pragma unroll
    for (int r = 0; r < 8; r++) {
        int row = row0 + tm * 8 + r;
#pragma unroll
        for (int c = 0; c < 8; c += 4) {
            int col = col0 + tn * 8 + c;
            float4 v;
            v.x = acc[r][c + 0];
            v.y = acc[r][c + 1];
            v.z = acc[r][c + 2];
            v.w = acc[r][c + 3];
            if (bias) {
                float4 bb = *(const float4*)&bias[col];
                v.x += bb.x; v.y += bb.y; v.z += bb.z; v.w += bb.w;
            }
            *(float4*)&C[(size_t)row * N + col] = v;
        }
    }
}

__global__ __launch_bounds__(256)
void softmax_partial_kernel(const float* __restrict__ scores)
{
    int j  = blockIdx.x * 256 + threadIdx.x;
    int i0 = blockIdx.y * (NS_ / RSPLIT);
    float m = -INFINITY, s = 0.0f;
#pragma unroll 4
    for (int i = i0; i < i0 + NS_ / RSPLIT; i++) {
        float x = scores[(size_t)i * NK_ + j];
        if (x <= m) {
            s += __expf(x - m);
        } else {
            s = s * __expf(m - x) + 1.0f;
            m = x;
        }
    }
    g_pmax[blockIdx.y * NK_ + j] = m;
    g_psum[blockIdx.y * NK_ + j] = s;
}

__global__ __launch_bounds__(256)
void softmax_combine_kernel()
{
    int j = blockIdx.x * 256 + threadIdx.x;
    float m = -INFINITY, s = 0.0f;
#pragma unroll
    for (int r = 0; r < RSPLIT; r++) {
        float pm = g_pmax[r * NK_ + j];
        float ps = g_psum[r * NK_ + j];
        if (pm <= m) {
            s += ps * __expf(pm - m);
        } else {
            s = s * __expf(m - pm) + ps;
            m = pm;
        }
    }
    g_cmax[j] = m;
    g_cinv[j] = 1.0f / s;
}

__global__ __launch_bounds__(256)
void softmax_normalize_kernel(float* __restrict__ attn)
{
    size_t idx = (size_t)blockIdx.x * 256 + threadIdx.x;
    int j4 = (int)(idx % (NK_ / 4));
    float4 x  = ((float4*)attn)[idx];
    float4 mm = *(const float4*)&g_cmax[j4 * 4];
    float4 ii = *(const float4*)&g_cinv[j4 * 4];
    x.x = __expf(x.x - mm.x) * ii.x;
    x.y = __expf(x.y - mm.y) * ii.y;
    x.z = __expf(x.z - mm.z) * ii.z;
    x.w = __expf(x.w - mm.w) * ii.w;
    ((float4*)attn)[idx] = x;
}

extern "C" void kernel_launch(void* const* d_in, const int* in_sizes, int n_in,
                              void* d_out, int out_size)
{
    (void)in_sizes; (void)n_in; (void)out_size;
    const float* sent  = (const float*)d_in[0];   // [NS, SENT]
    const float* knowl = (const float*)d_in[1];   // [NK, 2H]
    const float* Ws    = (const float*)d_in[2];   // [HID, SENT]
    const float* bs    = (const float*)d_in[3];   // [HID]
    const float* Wk    = (const float*)d_in[4];   // [HID, 2H]
    const float* bk    = (const float*)d_in[5];   // [HID]

    float* attn  = (float*)d_out;                        // [NS, NK]
    float* fused = (float*)d_out + (size_t)NS_ * NK_;    // [NS, 2H]

    float* dS; cudaGetSymbolAddress((void**)&dS, g_S);
    float* dK; cudaGetSymbolAddress((void**)&dK, g_K);

    dim3 blk(256);

    // S = sent @ Ws^T + bs   [NS, HID]
    sgemm_kernel<true><<<dim3(HID_ / 128, NS_ / 128), blk>>>(
        sent, Ws, bs, dS, NS_, HID_, SENT_);

    // K = knowl @ Wk^T + bk  [NK, HID]
    sgemm_kernel<true><<<dim3(HID_ / 128, NK_ / 128), blk>>>(
        knowl, Wk, bk, dK, NK_, HID_, TWOH_);

    // scores = S @ K^T       [NS, NK] -> attn region of d_out
    sgemm_kernel<true><<<dim3(NK_ / 128, NS_ / 128), blk>>>(
        dS, dK, nullptr, attn, NS_, NK_, HID_);

    // softmax over axis 0 (columns)
    softmax_partial_kernel<<<dim3(NK_ / 256, RSPLIT), blk>>>(attn);
    softmax_combine_kernel<<<dim3(NK_ / 256), blk>>>();
    softmax_normalize_kernel<<<dim3((unsigned)((size_t)NS_ * NK_ / 4 / 256)), blk>>>(attn);

    // fused = attn @ V       [NS, 2H]
    sgemm_kernel<false><<<dim3(TWOH_ / 128, NS_ / 128), blk>>>(
        attn, knowl, nullptr, fused, NS_, TWOH_, NK_);
}